// round 7
// baseline (speedup 1.0000x reference)
#include <cuda_runtime.h>
#include <cuda_bf16.h>
#include <math.h>
#include <stdint.h>

// Problem constants
#define EMBED  512
#define HIDDEN 512
#define VOCAB  10000
#define BATCH  64
#define SEQT   32
#define GATES  (4 * HIDDEN)   // 2048
#define MROWS  (SEQT * BATCH) // 2048
#define KDIM   512

#define SSTR   40             // padded smem row stride in halfs
#define TILEH  (128 * SSTR)   // halfs per tile buffer
#define TILEB  (TILEH * 2)    // bytes per tile buffer

// ---------------- scratch (device globals; no allocation allowed) -------------
__device__ __align__(16) float g_xgates[MROWS * GATES];
__device__ __align__(16) float g_h[BATCH * HIDDEN];
__device__ __align__(16) float g_c[BATCH * HIDDEN];
__device__ int g_cap_is64;

// split operand storage
__device__ __align__(16) __nv_bfloat16 g_xs1[MROWS * EMBED];
__device__ __align__(16) __nv_bfloat16 g_xs2[MROWS * EMBED];
__device__ __align__(16) __nv_bfloat16 g_xs3[MROWS * EMBED];
__device__ __align__(16) __nv_bfloat16 g_hs1[MROWS * HIDDEN];
__device__ __align__(16) __nv_bfloat16 g_hs2[MROWS * HIDDEN];
__device__ __align__(16) __nv_bfloat16 g_Wih1[GATES * EMBED];
__device__ __align__(16) __nv_bfloat16 g_Wih2[GATES * EMBED];
__device__ __align__(16) __nv_bfloat16 g_Wih3[GATES * EMBED];
__device__ __align__(16) __nv_bfloat16 g_Wfc1[VOCAB * HIDDEN];
__device__ __align__(16) __nv_bfloat16 g_Wfc2[VOCAB * HIDDEN];

// ---------------- split helpers ------------------------------------------------
__device__ __forceinline__ void split2p(float x, float y, uint32_t& o1, uint32_t& o2) {
    __nv_bfloat162 h = __floats2bfloat162_rn(x, y);
    float2 hf = __bfloat1622float2(h);
    __nv_bfloat162 l = __floats2bfloat162_rn(x - hf.x, y - hf.y);
    o1 = *(uint32_t*)&h;
    o2 = *(uint32_t*)&l;
}
__device__ __forceinline__ void split3p(float x, float y,
                                        uint32_t& o1, uint32_t& o2, uint32_t& o3) {
    __nv_bfloat162 h = __floats2bfloat162_rn(x, y);
    float2 hf = __bfloat1622float2(h);
    float rx = x - hf.x, ry = y - hf.y;
    __nv_bfloat162 m = __floats2bfloat162_rn(rx, ry);
    float2 mf = __bfloat1622float2(m);
    __nv_bfloat162 l = __floats2bfloat162_rn(rx - mf.x, ry - mf.y);
    o1 = *(uint32_t*)&h;
    o2 = *(uint32_t*)&m;
    o3 = *(uint32_t*)&l;
}

__device__ __forceinline__ uint32_t smem_u32(const void* p) {
    uint32_t a;
    asm("{ .reg .u64 t; cvta.to.shared.u64 t, %1; cvt.u32.u64 %0, t; }" : "=r"(a) : "l"(p));
    return a;
}

#define LDSM_X4(r0, r1, r2, r3, addr) \
    asm volatile("ldmatrix.sync.aligned.m8n8.x4.shared.b16 {%0,%1,%2,%3}, [%4];" \
        : "=r"(r0), "=r"(r1), "=r"(r2), "=r"(r3) : "r"(addr))

#define MMA_BF16(d, a, b) \
    asm volatile("mma.sync.aligned.m16n8k16.row.col.f32.bf16.bf16.f32 " \
        "{%0,%1,%2,%3}, {%4,%5,%6,%7}, {%8,%9}, {%0,%1,%2,%3};" \
        : "+f"((d)[0]), "+f"((d)[1]), "+f"((d)[2]), "+f"((d)[3]) \
        : "r"((a)[0]), "r"((a)[1]), "r"((a)[2]), "r"((a)[3]), \
          "r"((b)[0]), "r"((b)[1]))

// ---------------- captions dtype detection ------------------------------------
__global__ void detect_captions_kernel(const void* __restrict__ captions)
{
    const long long* c64 = (const long long*)captions;
    int bad = 0;
    for (int i = threadIdx.x; i < BATCH * SEQT; i += 32) {
        long long v = c64[i];
        if (v < 0 || v >= VOCAB) bad = 1;
    }
    #pragma unroll
    for (int s = 16; s > 0; s >>= 1)
        bad |= __shfl_xor_sync(0xffffffffu, bad, s);
    if (threadIdx.x == 0) g_cap_is64 = bad ? 0 : 1;
}

// ---------------- gather: build xs as 3-way split bf16 -------------------------
__global__ void gather_xs_kernel(const float* __restrict__ features,
                                 const void* __restrict__ captions,
                                 const float* __restrict__ emb_table)
{
    int m = blockIdx.x;
    int t = m >> 6;
    int b = m & 63;
    const float* src;
    if (t == 0) {
        src = features + (size_t)b * EMBED;
    } else {
        int idx = b * SEQT + (t - 1);
        long long tok = g_cap_is64 ? ((const long long*)captions)[idx]
                                   : (long long)((const int*)captions)[idx];
        if (tok < 0) tok = 0;
        if (tok >= VOCAB) tok = VOCAB - 1;
        src = emb_table + (size_t)tok * EMBED;
    }
    float4 v = ((const float4*)src)[threadIdx.x];
    uint32_t a1, a2, a3, b1, b2, b3;
    split3p(v.x, v.y, a1, a2, a3);
    split3p(v.z, v.w, b1, b2, b3);
    size_t off = (size_t)m * EMBED + threadIdx.x * 4;
    *(uint2*)(g_xs1 + off) = make_uint2(a1, b1);
    *(uint2*)(g_xs2 + off) = make_uint2(a2, b2);
    *(uint2*)(g_xs3 + off) = make_uint2(a3, b3);
}

// ---------------- weight split kernels -----------------------------------------
__global__ void split2_kernel(const float* __restrict__ src,
                              __nv_bfloat16* __restrict__ s1,
                              __nv_bfloat16* __restrict__ s2, int n4)
{
    int i = blockIdx.x * blockDim.x + threadIdx.x;
    if (i < n4) {
        float4 v = ((const float4*)src)[i];
        uint32_t a1, a2, b1, b2;
        split2p(v.x, v.y, a1, a2);
        split2p(v.z, v.w, b1, b2);
        *(uint2*)(s1 + (size_t)i * 4) = make_uint2(a1, b1);
        *(uint2*)(s2 + (size_t)i * 4) = make_uint2(a2, b2);
    }
}
__global__ void split3_kernel(const float* __restrict__ src,
                              __nv_bfloat16* __restrict__ s1,
                              __nv_bfloat16* __restrict__ s2,
                              __nv_bfloat16* __restrict__ s3, int n4)
{
    int i = blockIdx.x * blockDim.x + threadIdx.x;
    if (i < n4) {
        float4 v = ((const float4*)src)[i];
        uint32_t a1, a2, a3, b1, b2, b3;
        split3p(v.x, v.y, a1, a2, a3);
        split3p(v.z, v.w, b1, b2, b3);
        *(uint2*)(s1 + (size_t)i * 4) = make_uint2(a1, b1);
        *(uint2*)(s2 + (size_t)i * 4) = make_uint2(a2, b2);
        *(uint2*)(s3 + (size_t)i * 4) = make_uint2(a3, b3);
    }
}

// =============== split-bf16 ldmatrix GEMM: C = A * B^T (+bias) =================
// CTA tile 128x128, 8 warps (2x4) of 64x32, K chunked by 32.
// NSPLIT=2: passes {00,01,10}.  NSPLIT=3: passes {00,01,02,10,11,20}.
// mode 0: C[m*N+n]   mode 1: m=t*64+b -> C[(b*32+t)*N+n]

template<int NSPLIT, int NPASS>
__global__ void __launch_bounds__(256) gemm_ldsm_kernel(
    const __nv_bfloat16* __restrict__ A0, const __nv_bfloat16* __restrict__ A1,
    const __nv_bfloat16* __restrict__ A2,
    const __nv_bfloat16* __restrict__ B0, const __nv_bfloat16* __restrict__ B1,
    const __nv_bfloat16* __restrict__ B2,
    float* __restrict__ C, int N,
    const float* __restrict__ bias1, const float* __restrict__ bias2, int mode)
{
    extern __shared__ __nv_bfloat16 dsm[];
    __nv_bfloat16* sA = dsm;                      // [NSPLIT][TILEH]
    __nv_bfloat16* sB = dsm + NSPLIT * TILEH;
    const __nv_bfloat16* As[3] = { A0, A1, A2 };
    const __nv_bfloat16* Bs[3] = { B0, B1, B2 };

    const int tid  = threadIdx.x;
    const int wid  = tid >> 5;
    const int lane = tid & 31;
    const int gq   = lane >> 2;
    const int tq   = lane & 3;
    const int m0 = blockIdx.y * 128;
    const int n0 = blockIdx.x * 128;
    const int wm = (wid & 1) * 64;
    const int wn = (wid >> 1) * 32;

    const uint32_t sA_u = smem_u32(sA);
    const uint32_t sB_u = smem_u32(sB);
    // ldmatrix per-lane row offsets (bytes)
    const uint32_t aoff = ((wm + (lane & 15)) * SSTR + 8 * (lane >> 4)) * 2;
    const uint32_t boff = ((wn + (lane & 7) + 8 * (lane >> 4)) * SSTR
                           + 8 * ((lane >> 3) & 1)) * 2;

    float acc[4][4][4];
    #pragma unroll
    for (int mi = 0; mi < 4; mi++)
        #pragma unroll
        for (int ni = 0; ni < 4; ni++)
            #pragma unroll
            for (int r = 0; r < 4; r++) acc[mi][ni][r] = 0.0f;

    const int lr = tid >> 1;
    const int lc = (tid & 1) * 16;
    const bool bvalid = (n0 + lr) < N;
    const uint4 zz = make_uint4(0, 0, 0, 0);

    constexpr int PA2[3] = {0, 0, 1},          PB2[3] = {0, 1, 0};
    constexpr int PA3[6] = {0, 0, 0, 1, 1, 2}, PB3[6] = {0, 1, 2, 0, 1, 0};

    for (int k0 = 0; k0 < KDIM; k0 += 32) {
        #pragma unroll
        for (int s = 0; s < NSPLIT; s++) {
            const __nv_bfloat16* pa = As[s] + (size_t)(m0 + lr) * KDIM + k0 + lc;
            uint4 v0 = ((const uint4*)pa)[0];
            uint4 v1 = ((const uint4*)pa)[1];
            *(uint4*)(sA + s * TILEH + lr * SSTR + lc)     = v0;
            *(uint4*)(sA + s * TILEH + lr * SSTR + lc + 8) = v1;
            const __nv_bfloat16* pb = Bs[s] + (size_t)(n0 + lr) * KDIM + k0 + lc;
            uint4 w0 = bvalid ? ((const uint4*)pb)[0] : zz;
            uint4 w1 = bvalid ? ((const uint4*)pb)[1] : zz;
            *(uint4*)(sB + s * TILEH + lr * SSTR + lc)     = w0;
            *(uint4*)(sB + s * TILEH + lr * SSTR + lc + 8) = w1;
        }
        __syncthreads();

        #pragma unroll
        for (int ko = 0; ko < 32; ko += 16) {
            uint32_t af[4][4];
            uint32_t bf[4][2];
            #pragma unroll
            for (int p = 0; p < NPASS; p++) {
                const int pa = (NSPLIT == 2) ? PA2[p] : PA3[p];
                const int pb = (NSPLIT == 2) ? PB2[p] : PB3[p];
                const int paprev = (p == 0) ? -1 : ((NSPLIT == 2) ? PA2[p - 1] : PA3[p - 1]);
                if (pa != paprev) {
                    #pragma unroll
                    for (int mi = 0; mi < 4; mi++) {
                        uint32_t ad = sA_u + pa * TILEB + aoff + mi * (16 * SSTR * 2) + ko * 2;
                        LDSM_X4(af[mi][0], af[mi][1], af[mi][2], af[mi][3], ad);
                    }
                }
                #pragma unroll
                for (int nb = 0; nb < 2; nb++) {
                    uint32_t bd = sB_u + pb * TILEB + boff + nb * (16 * SSTR * 2) + ko * 2;
                    LDSM_X4(bf[2 * nb][0], bf[2 * nb][1], bf[2 * nb + 1][0], bf[2 * nb + 1][1], bd);
                }
                #pragma unroll
                for (int mi = 0; mi < 4; mi++)
                    #pragma unroll
                    for (int ni = 0; ni < 4; ni++)
                        MMA_BF16(acc[mi][ni], af[mi], bf[ni]);
            }
        }
        __syncthreads();
    }

    // ---- epilogue: bias + optional (b,t) permute --------------------------------
    #pragma unroll
    for (int mi = 0; mi < 4; mi++) {
        const int row = m0 + wm + mi * 16 + gq;
        size_t or0, or1;
        if (mode == 0) {
            or0 = (size_t)row;
            or1 = (size_t)(row + 8);
        } else {
            or0 = (size_t)((row & 63) * SEQT + (row >> 6));
            int r1 = row + 8;
            or1 = (size_t)((r1 & 63) * SEQT + (r1 >> 6));
        }
        #pragma unroll
        for (int ni = 0; ni < 4; ni++) {
            const int col = n0 + wn + ni * 8 + 2 * tq;
            if (col < N) {
                float bv0 = bias1[col], bv1 = bias1[col + 1];
                if (bias2) { bv0 += bias2[col]; bv1 += bias2[col + 1]; }
                float2 v0 = make_float2(acc[mi][ni][0] + bv0, acc[mi][ni][1] + bv1);
                float2 v1 = make_float2(acc[mi][ni][2] + bv0, acc[mi][ni][3] + bv1);
                *(float2*)(C + or0 * (size_t)N + col) = v0;
                *(float2*)(C + or1 * (size_t)N + col) = v1;
            }
        }
    }
}

// ---------------- fused LSTM step (fp32; grid 32x4 = 128 CTAs) -----------------
__device__ __forceinline__ float sigmoidf_(float x) {
    return 1.0f / (1.0f + expf(-x));
}

__global__ void lstm_step_kernel(const float* __restrict__ W_hh, int t)
{
    const int tx = threadIdx.x & 15;      // j within 16-tile
    const int ty = threadIdx.x >> 4;      // 0..7, handles 2 b-rows
    const int j  = blockIdx.x * 16 + tx;
    const int b0 = blockIdx.y * 16;

    float acc[4][2];
    #pragma unroll
    for (int g = 0; g < 4; g++) { acc[g][0] = 0.0f; acc[g][1] = 0.0f; }

    if (t > 0) {
        __shared__ float hsh[16][33];
        __shared__ float wsh[64][33];

        for (int k0 = 0; k0 < HIDDEN; k0 += 32) {
            {
                int idx = threadIdx.x;           // 0..127
                int bb = idx >> 3;               // 0..15
                int kq = (idx & 7) * 4;
                float4 v = *(const float4*)&g_h[(size_t)(b0 + bb) * HIDDEN + k0 + kq];
                hsh[bb][kq + 0] = v.x; hsh[bb][kq + 1] = v.y;
                hsh[bb][kq + 2] = v.z; hsh[bb][kq + 3] = v.w;
            }
            #pragma unroll
            for (int e = 0; e < 4; e++) {
                int idx = threadIdx.x + 128 * e;  // 0..511
                int row = idx >> 3;               // 0..63 = g*16 + jl
                int kq  = (idx & 7) * 4;
                int g   = row >> 4;
                int jl  = row & 15;
                int grow = g * HIDDEN + blockIdx.x * 16 + jl;
                float4 v = *(const float4*)&W_hh[(size_t)grow * HIDDEN + k0 + kq];
                wsh[row][kq + 0] = v.x; wsh[row][kq + 1] = v.y;
                wsh[row][kq + 2] = v.z; wsh[row][kq + 3] = v.w;
            }
            __syncthreads();

            #pragma unroll
            for (int kk = 0; kk < 32; kk++) {
                float h0 = hsh[ty * 2 + 0][kk];
                float h1 = hsh[ty * 2 + 1][kk];
                #pragma unroll
                for (int g = 0; g < 4; g++) {
                    float wv = wsh[g * 16 + tx][kk];
                    acc[g][0] = fmaf(wv, h0, acc[g][0]);
                    acc[g][1] = fmaf(wv, h1, acc[g][1]);
                }
            }
            __syncthreads();
        }
    }

    const float* xg = g_xgates + (size_t)t * BATCH * GATES;

    #pragma unroll
    for (int r = 0; r < 2; r++) {
        int b = b0 + ty * 2 + r;
        size_t gbase = (size_t)b * GATES + j;
        float gi = acc[0][r] + xg[gbase];
        float gf = acc[1][r] + xg[gbase + HIDDEN];
        float gg = acc[2][r] + xg[gbase + 2 * HIDDEN];
        float go = acc[3][r] + xg[gbase + 3 * HIDDEN];

        float i_ = sigmoidf_(gi);
        float f_ = sigmoidf_(gf);
        float g_ = tanhf(gg);
        float o_ = sigmoidf_(go);

        size_t hidx = (size_t)b * HIDDEN + j;
        float cold = (t == 0) ? 0.0f : g_c[hidx];
        float cn = f_ * cold + i_ * g_;
        float hn = o_ * tanhf(cn);
        g_c[hidx] = cn;
        g_h[hidx] = hn;

        // hs 2-way split for the FC GEMM
        size_t off = (size_t)t * BATCH * HIDDEN + hidx;
        __nv_bfloat16 hh = __float2bfloat16(hn);
        g_hs1[off] = hh;
        g_hs2[off] = __float2bfloat16(hn - __bfloat162float(hh));
    }
}

// ---------------- launch ------------------------------------------------------
extern "C" void kernel_launch(void* const* d_in, const int* in_sizes, int n_in,
                              void* d_out, int out_size)
{
    const float* features  = (const float*)d_in[0];
    const void*  captions  = d_in[1];
    const float* emb_table = (const float*)d_in[2];
    const float* W_ih      = (const float*)d_in[3];
    const float* W_hh      = (const float*)d_in[4];
    const float* b_ih      = (const float*)d_in[5];
    const float* b_hh      = (const float*)d_in[6];
    const float* W_fc      = (const float*)d_in[7];
    const float* b_fc      = (const float*)d_in[8];
    float*       out       = (float*)d_out;

    float* xg_p;  cudaGetSymbolAddress((void**)&xg_p, g_xgates);
    __nv_bfloat16 *xs1, *xs2, *xs3, *hs1, *hs2, *wi1, *wi2, *wi3, *wf1, *wf2;
    cudaGetSymbolAddress((void**)&xs1, g_xs1);
    cudaGetSymbolAddress((void**)&xs2, g_xs2);
    cudaGetSymbolAddress((void**)&xs3, g_xs3);
    cudaGetSymbolAddress((void**)&hs1, g_hs1);
    cudaGetSymbolAddress((void**)&hs2, g_hs2);
    cudaGetSymbolAddress((void**)&wi1, g_Wih1);
    cudaGetSymbolAddress((void**)&wi2, g_Wih2);
    cudaGetSymbolAddress((void**)&wi3, g_Wih3);
    cudaGetSymbolAddress((void**)&wf1, g_Wfc1);
    cudaGetSymbolAddress((void**)&wf2, g_Wfc2);

    const int S3 = 6 * TILEB;   // 61440
    const int S2 = 4 * TILEB;   // 40960
    static int attr_set = 0;
    if (!attr_set) {
        cudaFuncSetAttribute(gemm_ldsm_kernel<3, 6>,
                             cudaFuncAttributeMaxDynamicSharedMemorySize, S3);
        cudaFuncSetAttribute(gemm_ldsm_kernel<2, 3>,
                             cudaFuncAttributeMaxDynamicSharedMemorySize, S2);
        attr_set = 1;
    }

    // 0) captions dtype detection
    detect_captions_kernel<<<1, 32>>>(captions);

    // 1) gather xs (3-way split)
    gather_xs_kernel<<<MROWS, 128>>>(features, captions, emb_table);

    // 2) split weights
    {
        int n4 = GATES * EMBED / 4;
        split3_kernel<<<(n4 + 255) / 256, 256>>>(W_ih, wi1, wi2, wi3, n4);
        n4 = VOCAB * HIDDEN / 4;
        split2_kernel<<<(n4 + 255) / 256, 256>>>(W_fc, wf1, wf2, n4);
    }

    // 3) x_gates = xs @ W_ih^T + b_ih + b_hh  (3-split, 6 passes -> ~2^-27)
    {
        dim3 grid(GATES / 128, MROWS / 128);
        gemm_ldsm_kernel<3, 6><<<grid, 256, S3>>>(xs1, xs2, xs3, wi1, wi2, wi3,
                                                  xg_p, GATES, b_ih, b_hh, 0);
    }

    // 4) 32 recurrent steps
    {
        dim3 grid(HIDDEN / 16, BATCH / 16);
        for (int t = 0; t < SEQT; t++)
            lstm_step_kernel<<<grid, 128>>>(W_hh, t);
    }

    // 5) logits = hs @ W_fc^T + b_fc, permuted  (2-split, 3 passes)
    {
        dim3 grid((VOCAB + 127) / 128, MROWS / 128);
        gemm_ldsm_kernel<2, 3><<<grid, 256, S2>>>(hs1, hs2, nullptr, wf1, wf2, nullptr,
                                                  out, VOCAB, b_fc, nullptr, 1);
    }
}